// round 16
// baseline (speedup 1.0000x reference)
#include <cuda_runtime.h>
#include <cuda_bf16.h>
#include <cooperative_groups.h>

namespace cg = cooperative_groups;

#define T_DEC 64
#define TENC  256
#define Bv    32
#define Ev    256
#define Dv    512
#define NMEL  80
#define NCTA  128
#define NGRID 148
#define NTHR  512

// ------------------------------------------------------------------
// Device-global state
// ------------------------------------------------------------------
__device__ float g_hT[2][Dv * Bv];            // h ping-pong, k-major (GRU input)
__device__ float g_ctxT[2][Ev * Bv];          // ctx ping-pong, e-major (GRU input)
__device__ float g_hHist[T_DEC + 1][Bv * Dv]; // h_t history, b-major (proj + heads)
__device__ float g_ctxHist[T_DEC][Bv * Ev];   // ctx_t history, b-major (heads)
__device__ float g_decT[T_DEC][Ev * Bv];      // dec transposed: [t][e*32+b]
__device__ unsigned g_bar_cnt;
__device__ unsigned g_bar_gen;                // monotonic across replays (safe)

// ------------------------------------------------------------------
// f32x2 packed helpers (sm_103a FFMA2 path)
// ------------------------------------------------------------------
__device__ __forceinline__ unsigned long long pk2(float lo, float hi) {
    unsigned long long v;
    asm("mov.b64 %0, {%1,%2};" : "=l"(v) : "f"(lo), "f"(hi));
    return v;
}
__device__ __forceinline__ unsigned long long f2fma(
    unsigned long long a, unsigned long long b, unsigned long long c) {
    unsigned long long d;
    asm("fma.rn.f32x2 %0, %1, %2, %3;" : "=l"(d) : "l"(a), "l"(b), "l"(c));
    return d;
}
__device__ __forceinline__ float upk_sum(unsigned long long v) {
    float lo, hi;
    asm("mov.b64 {%0,%1}, %2;" : "=f"(lo), "=f"(hi) : "l"(v));
    return lo + hi;
}
__device__ __forceinline__ float fast_exp2(float x) {
    float y;
    asm("ex2.approx.ftz.f32 %0, %1;" : "=f"(y) : "f"(x));
    return y;
}

// ------------------------------------------------------------------
// Hierarchical grid barrier: cluster.sync fan-in, 32 leader atomics.
// ------------------------------------------------------------------
__device__ __forceinline__ void grid_bar(cg::cluster_group& cl, bool lead)
{
    __threadfence();
    cl.sync();
    if (lead) {
        unsigned gen = *((volatile unsigned*)&g_bar_gen);
        unsigned a = atomicAdd(&g_bar_cnt, 1u);
        if (a == 31) {
            g_bar_cnt = 0;
            __threadfence();
            atomicExch(&g_bar_gen, gen + 1u);
        } else {
            while (*((volatile unsigned*)&g_bar_gen) == gen) {}
        }
    }
    cl.sync();
    __threadfence();
}

// ------------------------------------------------------------------
// SMEM layout (floats). 57984 floats = 231,936 B  (<= 232,448 max dyn)
// ------------------------------------------------------------------
#define OFF_WGRU 0          // 96*128  GRU weight slice
#define OFF_A    12288      // 256*64  A slice * log2e, XOR-swizzled banks
#define OFF_WATT 28672      // 64*384  W_att e-slice, cols 0..383
#define OFF_GP   53248      // 96*32   GRU partials (DSMEM-exposed)
#define OFF_H    56320      // 512     h staging
#define OFF_PROJ 56832      // 64
#define OFF_RZ   56896      // 64
#define OFF_ZP   56960      // 512     Z / tw-half / ctx partials (reused)
#define OFF_TWP  57472      // 256     (DSMEM-exposed)
#define OFF_TW   57728      // 256
#define SMEM_FLOATS 57984
#define SMEM_BYTES  (SMEM_FLOATS * 4)

#define LOG2E 1.442695040888963f
#define LN2   0.693147180559945f

// XOR bank swizzle for s_A: conflict-free row AND column access
__device__ __forceinline__ int aidx(int t, int e) { return t * 64 + (e ^ (t & 31)); }

// ------------------------------------------------------------------
__global__ void __launch_bounds__(NTHR, 1) __cluster_dims__(4, 1, 1)
decoder_persistent(
    const float* __restrict__ dec, const float* __restrict__ A,
    const float* __restrict__ W_att,
    const float* __restrict__ W_ih, const float* __restrict__ W_hh,
    const float* __restrict__ W_mel, const float* __restrict__ b_mel,
    const float* __restrict__ W_gate, const float* __restrict__ b_gate,
    float* __restrict__ out)
{
    if (blockIdx.x >= NCTA) return;   // full clusters 32..36 all exit together

    extern __shared__ float sm[];
    float* s_Wg   = sm + OFF_WGRU;
    float* s_A    = sm + OFF_A;
    float* s_Wa   = sm + OFF_WATT;
    float* s_gp   = sm + OFF_GP;
    float* s_h    = sm + OFF_H;
    float* s_proj = sm + OFF_PROJ;
    float* s_rZ   = sm + OFF_RZ;
    float* s_zp   = sm + OFF_ZP;
    float* s_twp  = sm + OFF_TWP;
    float* s_tw   = sm + OFF_TW;

    const int tid  = threadIdx.x;
    const int lane = tid & 31;
    const int wid  = tid >> 5;
    const int cid  = blockIdx.x;
    const int b    = cid >> 2;          // attention: batch element (cluster id)
    const int q    = cid & 3;           // attention: e-quadrant / GRU: k-quarter base
    const int e0   = q * 64;

    cg::cluster_group cl = cg::this_cluster();
    const bool lead = (q == 0) && (tid == 0);
    const float gate_b = b_gate[0];

    // ================= init (once) =================
    // GRU weights: row r = g*16+dl (g 0..2 ih r/z/n, 3..5 hh), k-range q*128..+128
    {
        float4* dst = (float4*)s_Wg;
        for (int idx = tid; idx < 96 * 32; idx += NTHR) {
            int r = idx >> 5, c4 = idx & 31;
            int g = r >> 4, dl = r & 15;
            int d = (b << 4) + dl;
            const float* src = (g < 3)
                ? (W_ih + ((size_t)g * Dv + d) * 512)
                : (W_hh + ((size_t)(g - 3) * Dv + d) * 512);
            dst[idx] = ((const float4*)(src + q * 128))[c4];
        }
    }
    // A slice * log2e, XOR-swizzled
    for (int idx = tid; idx < TENC * 64; idx += NTHR) {
        int tt = idx >> 6, e = idx & 63;
        s_A[aidx(tt, e)] = A[(size_t)tt * (Bv * Ev) + b * Ev + e0 + e] * LOG2E;
    }
    // W_att e-slice, cols 0..383 resident
    {
        float4* dst = (float4*)s_Wa;
        for (int idx = tid; idx < 64 * 96; idx += NTHR) {
            int row = idx / 96, c4 = idx - row * 96;
            dst[row * 96 + c4] = ((const float4*)(W_att + (size_t)(e0 + row) * Dv))[c4];
        }
    }
    // dec transpose -> g_decT[t][e*32+b]
    for (int idx = cid * NTHR + tid; idx < T_DEC * Bv * Ev; idx += NCTA * NTHR) {
        int t = idx / (Bv * Ev);
        int rem = idx - t * (Bv * Ev);
        int bb = rem >> 8, e = rem & 255;
        g_decT[t][e * Bv + bb] = dec[idx];
    }
    grid_bar(cl, lead);

    // ================= step loop =================
    #pragma unroll 1
    for (int t = 0; t < T_DEC; t++) {
        const int par = t & 1;

        // ---------- Phase A: attention ----------
        if (t > 0) s_h[tid] = g_hHist[t][b * Dv + tid];
        __syncthreads();

        // proj[e] = h . W_att[e,:]: 16 warps x 4 rows, cols 0..383 SMEM + 384..511 L2
        if (t > 0) {
            const int rl = wid << 2;
            const float4* hp = (const float4*)s_h;
            const float4* s0 = (const float4*)(s_Wa + (rl + 0) * 384);
            const float4* s1 = (const float4*)(s_Wa + (rl + 1) * 384);
            const float4* s2 = (const float4*)(s_Wa + (rl + 2) * 384);
            const float4* s3 = (const float4*)(s_Wa + (rl + 3) * 384);
            const float4* g0 = (const float4*)(W_att + (size_t)(e0 + rl + 0) * Dv + 384);
            const float4* g1 = (const float4*)(W_att + (size_t)(e0 + rl + 1) * Dv + 384);
            const float4* g2 = (const float4*)(W_att + (size_t)(e0 + rl + 2) * Dv + 384);
            const float4* g3 = (const float4*)(W_att + (size_t)(e0 + rl + 3) * Dv + 384);
            float a0 = 0.f, a1 = 0.f, a2 = 0.f, a3 = 0.f;
            #pragma unroll
            for (int i = 0; i < 3; i++) {
                int k4 = lane + 32 * i;
                float4 h4 = hp[k4];
                float4 f0 = s0[k4], f1 = s1[k4], f2 = s2[k4], f3 = s3[k4];
                a0 = fmaf(f0.x, h4.x, fmaf(f0.y, h4.y, fmaf(f0.z, h4.z, fmaf(f0.w, h4.w, a0))));
                a1 = fmaf(f1.x, h4.x, fmaf(f1.y, h4.y, fmaf(f1.z, h4.z, fmaf(f1.w, h4.w, a1))));
                a2 = fmaf(f2.x, h4.x, fmaf(f2.y, h4.y, fmaf(f2.z, h4.z, fmaf(f2.w, h4.w, a2))));
                a3 = fmaf(f3.x, h4.x, fmaf(f3.y, h4.y, fmaf(f3.z, h4.z, fmaf(f3.w, h4.w, a3))));
            }
            {
                float4 h4 = hp[lane + 96];
                float4 f0 = g0[lane], f1 = g1[lane], f2 = g2[lane], f3 = g3[lane];
                a0 = fmaf(f0.x, h4.x, fmaf(f0.y, h4.y, fmaf(f0.z, h4.z, fmaf(f0.w, h4.w, a0))));
                a1 = fmaf(f1.x, h4.x, fmaf(f1.y, h4.y, fmaf(f1.z, h4.z, fmaf(f1.w, h4.w, a1))));
                a2 = fmaf(f2.x, h4.x, fmaf(f2.y, h4.y, fmaf(f2.z, h4.z, fmaf(f2.w, h4.w, a2))));
                a3 = fmaf(f3.x, h4.x, fmaf(f3.y, h4.y, fmaf(f3.z, h4.z, fmaf(f3.w, h4.w, a3))));
            }
            #pragma unroll
            for (int o = 16; o; o >>= 1) {
                a0 += __shfl_down_sync(0xffffffffu, a0, o);
                a1 += __shfl_down_sync(0xffffffffu, a1, o);
                a2 += __shfl_down_sync(0xffffffffu, a2, o);
                a3 += __shfl_down_sync(0xffffffffu, a3, o);
            }
            if (lane == 0) {
                s_proj[rl + 0] = a0; s_proj[rl + 1] = a1;
                s_proj[rl + 2] = a2; s_proj[rl + 3] = a3;
            }
        } else if (tid < 64) s_proj[tid] = 0.f;
        __syncthreads();

        // softmax pass 1: Z[e] partials (u recomputed later, not stored)
        const int ee = tid & 63, tg = tid >> 6;   // tg in 0..7
        {
            float p = s_proj[ee];
            float z = 0.f;
            #pragma unroll 8
            for (int ti = tg; ti < TENC; ti += 8)
                z += fast_exp2(s_A[aidx(ti, ee)] * p);
            s_zp[tid] = z;
        }
        __syncthreads();
        if (tid < 64) {
            float zz = 0.f;
            #pragma unroll
            for (int g = 0; g < 8; g++) zz += s_zp[g * 64 + tid];
            s_rZ[tid] = 1.f / zz;
        }
        __syncthreads();

        // tw[t] partials: 2 threads per t, 32 e's each (u recomputed)
        {
            const int tt = tid & 255, half = tid >> 8;
            const int eb = half * 32;
            float v = 0.f;
            #pragma unroll 8
            for (int j = 0; j < 32; j++) {
                int e = eb + j;
                float u = fast_exp2(s_A[aidx(tt, e)] * s_proj[e]);
                v = fmaf(u, s_rZ[e], v);
            }
            s_zp[half * 256 + tt] = v;
        }
        __syncthreads();
        if (tid < 256) s_twp[tid] = s_zp[tid] + s_zp[256 + tid];
        cl.sync();
        if (tid < 256) {
            float s = 0.f;
            #pragma unroll
            for (int r = 0; r < 4; r++) {
                const float* rp = cl.map_shared_rank(s_twp, r);
                s += rp[tid];
            }
            s_tw[tid] = s;
        }
        cl.sync();

        // ctx[e] = ln2 * sum_t tw[t] * a'[t,e]
        {
            float acc = 0.f;
            #pragma unroll 8
            for (int ti = tg; ti < TENC; ti += 8)
                acc = fmaf(s_tw[ti], s_A[aidx(ti, ee)], acc);
            s_zp[tid] = acc;
        }
        __syncthreads();
        if (tid < 64) {
            float c = 0.f;
            #pragma unroll
            for (int g = 0; g < 8; g++) c += s_zp[g * 64 + tid];
            c *= LN2;
            g_ctxHist[t][b * Ev + e0 + tid] = c;
            g_ctxT[par][(e0 + tid) * Bv + b] = c;
        }
        grid_bar(cl, lead);

        // ---------- Phase B: GRU (cluster owns 16 dims; 4 row-groups x 4 k-quarters) ----------
        float psum[24];
        const int rg = wid & 3;           // row-group: 24 rows
        const int kh = wid >> 2;          // k-quarter (32 k) within CTA's 128
        {
            const int r0 = rg * 24;
            const int kabs0 = q * 128 + kh * 32;

            bool zsrc = false;
            const float* src;
            if (rg < 2) {
                if (kabs0 < 256) {
                    zsrc = (t == 0);
                    src = g_decT[(t > 0) ? (t - 1) : 0] + kabs0 * Bv;
                } else {
                    src = g_ctxT[par] + (kabs0 - 256) * Bv;
                }
            } else {
                zsrc = (t == 0);
                src = g_hT[par] + kabs0 * Bv;
            }

            unsigned long long acc2[24];
            #pragma unroll
            for (int j = 0; j < 24; j++) acc2[j] = 0ull;

            const float* wbase = s_Wg + r0 * 128 + kh * 32;
            #pragma unroll 2
            for (int kk = 0; kk < 32; kk += 4) {
                float v0 = zsrc ? 0.f : src[(kk + 0) * Bv + lane];
                float v1 = zsrc ? 0.f : src[(kk + 1) * Bv + lane];
                float v2 = zsrc ? 0.f : src[(kk + 2) * Bv + lane];
                float v3 = zsrc ? 0.f : src[(kk + 3) * Bv + lane];
                unsigned long long p01 = pk2(v0, v1), p23 = pk2(v2, v3);
                #pragma unroll
                for (int j = 0; j < 24; j++) {
                    ulonglong2 wp = *(const ulonglong2*)(wbase + j * 128 + kk);
                    acc2[j] = f2fma(wp.x, p01, acc2[j]);
                    acc2[j] = f2fma(wp.y, p23, acc2[j]);
                }
            }
            #pragma unroll
            for (int j = 0; j < 24; j++) psum[j] = upk_sum(acc2[j]);
        }
        // merge 4 k-quarters (serialized adds)
        {
            const int r0 = rg * 24;
            if (kh == 0) {
                #pragma unroll
                for (int j = 0; j < 24; j++) s_gp[(r0 + j) * 32 + lane] = psum[j];
            }
            __syncthreads();
            if (kh == 1) {
                #pragma unroll
                for (int j = 0; j < 24; j++) s_gp[(r0 + j) * 32 + lane] += psum[j];
            }
            __syncthreads();
            if (kh == 2) {
                #pragma unroll
                for (int j = 0; j < 24; j++) s_gp[(r0 + j) * 32 + lane] += psum[j];
            }
            __syncthreads();
            if (kh == 3) {
                #pragma unroll
                for (int j = 0; j < 24; j++) s_gp[(r0 + j) * 32 + lane] += psum[j];
            }
        }
        cl.sync();

        // epilogue: CTA q handles local dims [4q, 4q+4), summing the 4 rank partials
        if (tid < 128) {
            const int dl = q * 4 + (tid >> 5);
            const int bb = lane;
            float G[6];
            #pragma unroll
            for (int g = 0; g < 6; g++) {
                float s = 0.f;
                #pragma unroll
                for (int r = 0; r < 4; r++) {
                    const float* rp = cl.map_shared_rank(s_gp, r);
                    s += rp[(g * 16 + dl) * 32 + bb];
                }
                G[g] = s;
            }
            float rg2 = 1.f / (1.f + __expf(-(G[0] + G[3])));
            float zg  = 1.f / (1.f + __expf(-(G[1] + G[4])));
            float ng  = tanhf(G[2] + rg2 * G[5]);
            int d = (b << 4) + dl;
            float hold = (t == 0) ? 0.f : g_hT[par][d * Bv + bb];
            float hnew = fmaxf((1.f - zg) * ng + zg * hold, 0.f);
            g_hT[par ^ 1][d * Bv + bb] = hnew;
            g_hHist[t + 1][bb * Dv + d] = hnew;
        }
        grid_bar(cl, lead);
    }

    // ================= final heads pass =================
    // CTA covers 16 (t,b) pairs sharing one t: tP = cid/2, b in [b0, b0+16)
    {
        float* s_WC = sm;               // 27*768 floats (over s_Wg + s_A head)
        float* s_P  = sm + 20736;       // 16*772 floats (over s_A tail / s_Wa head)
        const int tP = cid >> 1;
        const int b0 = (cid & 1) * 16;

        for (int idx = tid; idx < 16 * 768; idx += NTHR) {
            int p = idx / 768, i = idx - p * 768;
            int bb = b0 + p;
            float v = (i < 256) ? g_ctxHist[tP][bb * Ev + i]
                                : g_hHist[tP + 1][bb * Dv + (i - 256)];
            s_P[p * 772 + i] = v;
        }
        __syncthreads();

        #pragma unroll 1
        for (int chunk = 0; chunk < 3; chunk++) {
            const int r0 = chunk * 27;
            for (int idx = tid; idx < 27 * 768; idx += NTHR) {
                int j = idx / 768, k = idx - j * 768;
                int rg2 = r0 + j;
                s_WC[idx] = (rg2 < 80) ? W_mel[(size_t)rg2 * 768 + k] : W_gate[k];
            }
            __syncthreads();

            for (int d = tid; d < 27 * 16; d += NTHR) {
                int j = d >> 4, p = d & 15;
                const float4* wr = (const float4*)(s_WC + j * 768);
                const float4* ch = (const float4*)(s_P + p * 772);
                float acc = 0.f;
                #pragma unroll 8
                for (int k4 = 0; k4 < 192; k4++) {
                    float4 w = wr[k4];
                    float4 c = ch[k4];
                    acc = fmaf(w.x, c.x, fmaf(w.y, c.y, fmaf(w.z, c.z, fmaf(w.w, c.w, acc))));
                }
                int rg2 = r0 + j;
                int bb = b0 + p;
                if (rg2 < 80) out[bb * (NMEL * T_DEC) + rg2 * T_DEC + tP] = acc + b_mel[rg2];
                else          out[NMEL * T_DEC * Bv + bb * T_DEC + tP]   = acc + gate_b;
            }
            __syncthreads();
        }
    }
}

// ------------------------------------------------------------------
extern "C" void kernel_launch(void* const* d_in, const int* in_sizes, int n_in,
                              void* d_out, int out_size)
{
    const float* dec    = (const float*)d_in[0];
    const float* A      = (const float*)d_in[1];
    const float* W_att  = (const float*)d_in[2];
    const float* W_ih   = (const float*)d_in[3];
    const float* W_hh   = (const float*)d_in[4];
    const float* W_mel  = (const float*)d_in[5];
    const float* b_mel  = (const float*)d_in[6];
    const float* W_gate = (const float*)d_in[7];
    const float* b_gate = (const float*)d_in[8];
    float* out = (float*)d_out;

    cudaFuncSetAttribute(decoder_persistent,
                         cudaFuncAttributeMaxDynamicSharedMemorySize, SMEM_BYTES);

    decoder_persistent<<<NGRID, NTHR, SMEM_BYTES>>>(
        dec, A, W_att, W_ih, W_hh, W_mel, b_mel, W_gate, b_gate, out);
}

// round 17
// speedup vs baseline: 1.0297x; 1.0297x over previous
#include <cuda_runtime.h>
#include <cuda_bf16.h>
#include <cooperative_groups.h>

namespace cg = cooperative_groups;

#define T_DEC 64
#define TENC  256
#define Bv    32
#define Ev    256
#define Dv    512
#define NMEL  80
#define NCTA  128
#define NGRID 148
#define NTHR  256
#define NSLOT 129   // slot 2t = ctx-ready(t), 2t+1 = h-ready(t), 128 = init

// ------------------------------------------------------------------
// Device-global state
// ------------------------------------------------------------------
__device__ float g_hT[2][Dv * Bv];            // h ping-pong, k-major (GRU input)
__device__ float g_ctxT[2][Ev * Bv];          // ctx ping-pong, e-major (GRU input)
__device__ float g_hHist[T_DEC + 1][Bv * Dv]; // h_t history, b-major (proj + heads)
__device__ float g_ctxHist[T_DEC][Bv * Ev];   // ctx_t history, b-major (heads)
__device__ float g_decT[T_DEC][Ev * Bv];      // dec transposed: [t][e*32+b]
__device__ volatile unsigned g_slots[NSLOT];  // one-shot arrival counters (reset at end)
__device__ unsigned g_bar_cnt;                // final gen-barrier (replay-safe)
__device__ unsigned g_bar_gen;

// ------------------------------------------------------------------
// f32x2 packed helpers (sm_103a FFMA2 path)
// ------------------------------------------------------------------
__device__ __forceinline__ unsigned long long pk2(float lo, float hi) {
    unsigned long long v;
    asm("mov.b64 %0, {%1,%2};" : "=l"(v) : "f"(lo), "f"(hi));
    return v;
}
__device__ __forceinline__ unsigned long long f2fma(
    unsigned long long a, unsigned long long b, unsigned long long c) {
    unsigned long long d;
    asm("fma.rn.f32x2 %0, %1, %2, %3;" : "=l"(d) : "l"(a), "l"(b), "l"(c));
    return d;
}
__device__ __forceinline__ float upk_sum(unsigned long long v) {
    float lo, hi;
    asm("mov.b64 {%0,%1}, %2;" : "=f"(lo), "=f"(hi) : "l"(v));
    return lo + hi;
}
__device__ __forceinline__ float fast_exp2(float x) {
    float y;
    asm("ex2.approx.ftz.f32 %0, %1;" : "=f"(y) : "f"(x));
    return y;
}

// ------------------------------------------------------------------
// Split arrive/wait slot barrier (128 CTA arrivals per slot)
// ------------------------------------------------------------------
__device__ __forceinline__ void slot_arrive(int slot)
{
    __threadfence();
    __syncthreads();
    if (threadIdx.x == 0) {
        unsigned one = 1u;
        asm volatile("red.global.add.u32 [%0], %1;"
                     :: "l"((unsigned*)&g_slots[slot]), "r"(one) : "memory");
    }
}
__device__ __forceinline__ void slot_wait(int slot)
{
    if (threadIdx.x == 0) {
        while (g_slots[slot] < NCTA) {}
    }
    __syncthreads();
    __threadfence();
}

// Final gen-based barrier (monotonic across replays; guards slot reset)
__device__ __forceinline__ void gen_bar(cg::cluster_group& cl, bool lead)
{
    __threadfence();
    cl.sync();
    if (lead) {
        unsigned gen = *((volatile unsigned*)&g_bar_gen);
        unsigned a = atomicAdd(&g_bar_cnt, 1u);
        if (a == 31) {
            g_bar_cnt = 0;
            __threadfence();
            atomicExch(&g_bar_gen, gen + 1u);
        } else {
            while (*((volatile unsigned*)&g_bar_gen) == gen) {}
        }
    }
    cl.sync();
    __threadfence();
}

// ------------------------------------------------------------------
// SMEM layout (floats). 57984 floats = 231,936 B  (<= 232,448 max dyn)
// ------------------------------------------------------------------
#define OFF_WGRU 0          // 96*128  GRU weight slice
#define OFF_A    12288      // 256*65  A slice * log2e, padded stride 65
#define OFF_WATT 28928      // 64*384  W_att e-slice, cols 0..383
#define OFF_GP   53504      // 96*32   GRU partials (DSMEM-exposed)
#define OFF_H    56576      // 512     h staging
#define OFF_PROJ 57088      // 64
#define OFF_RZ   57152      // 64
#define OFF_ZP   57216      // 256
#define OFF_TWP  57472      // 256     (DSMEM-exposed)
#define OFF_TW   57728      // 256
#define SMEM_FLOATS 57984
#define SMEM_BYTES  (SMEM_FLOATS * 4)

#define LOG2E 1.442695040888963f
#define LN2   0.693147180559945f

// 24-row x 64-k GEMV partial with packed f32x2 FMA
__device__ __forceinline__ void gru_gemv24(
    const float* __restrict__ src, bool zsrc,
    const float* __restrict__ wbase, int lane, float* __restrict__ psum)
{
    unsigned long long acc2[24];
    #pragma unroll
    for (int j = 0; j < 24; j++) acc2[j] = 0ull;
    #pragma unroll 2
    for (int kk = 0; kk < 64; kk += 4) {
        float v0 = zsrc ? 0.f : src[(kk + 0) * Bv + lane];
        float v1 = zsrc ? 0.f : src[(kk + 1) * Bv + lane];
        float v2 = zsrc ? 0.f : src[(kk + 2) * Bv + lane];
        float v3 = zsrc ? 0.f : src[(kk + 3) * Bv + lane];
        unsigned long long p01 = pk2(v0, v1), p23 = pk2(v2, v3);
        #pragma unroll
        for (int j = 0; j < 24; j++) {
            ulonglong2 wp = *(const ulonglong2*)(wbase + j * 128 + kk);
            acc2[j] = f2fma(wp.x, p01, acc2[j]);
            acc2[j] = f2fma(wp.y, p23, acc2[j]);
        }
    }
    #pragma unroll
    for (int j = 0; j < 24; j++) psum[j] = upk_sum(acc2[j]);
}

// ------------------------------------------------------------------
__global__ void __launch_bounds__(NTHR, 1) __cluster_dims__(4, 1, 1)
decoder_persistent(
    const float* __restrict__ dec, const float* __restrict__ A,
    const float* __restrict__ W_att,
    const float* __restrict__ W_ih, const float* __restrict__ W_hh,
    const float* __restrict__ W_mel, const float* __restrict__ b_mel,
    const float* __restrict__ W_gate, const float* __restrict__ b_gate,
    float* __restrict__ out)
{
    if (blockIdx.x >= NCTA) return;   // clusters 32..36 exit whole

    extern __shared__ float sm[];
    float* s_Wg   = sm + OFF_WGRU;
    float* s_A    = sm + OFF_A;
    float* s_Wa   = sm + OFF_WATT;
    float* s_gp   = sm + OFF_GP;
    float* s_h    = sm + OFF_H;
    float* s_proj = sm + OFF_PROJ;
    float* s_rZ   = sm + OFF_RZ;
    float* s_zp   = sm + OFF_ZP;
    float* s_twp  = sm + OFF_TWP;
    float* s_tw   = sm + OFF_TW;

    const int tid  = threadIdx.x;
    const int lane = tid & 31;
    const int wid  = tid >> 5;
    const int cid  = blockIdx.x;
    const int b    = cid >> 2;          // attention: batch element (cluster id)
    const int q    = cid & 3;           // attention: e-quadrant / GRU: k-quarter
    const int e0   = q * 64;

    cg::cluster_group cl = cg::this_cluster();
    const bool lead = (q == 0) && (tid == 0);
    const float gate_b = b_gate[0];

    // ================= init (once) =================
    {
        float4* dst = (float4*)s_Wg;
        for (int idx = tid; idx < 96 * 32; idx += NTHR) {
            int r = idx >> 5, c4 = idx & 31;
            int g = r >> 4, dl = r & 15;
            int d = (b << 4) + dl;
            const float* src = (g < 3)
                ? (W_ih + ((size_t)g * Dv + d) * 512)
                : (W_hh + ((size_t)(g - 3) * Dv + d) * 512);
            dst[idx] = ((const float4*)(src + q * 128))[c4];
        }
    }
    for (int idx = tid; idx < TENC * 64; idx += NTHR) {
        int tt = idx >> 6, e = idx & 63;
        s_A[tt * 65 + e] = A[(size_t)tt * (Bv * Ev) + b * Ev + e0 + e] * LOG2E;
    }
    {
        float4* dst = (float4*)s_Wa;
        for (int idx = tid; idx < 64 * 96; idx += NTHR) {
            int row = idx / 96, c4 = idx - row * 96;
            dst[row * 96 + c4] = ((const float4*)(W_att + (size_t)(e0 + row) * Dv))[c4];
        }
    }
    for (int idx = cid * NTHR + tid; idx < T_DEC * Bv * Ev; idx += NCTA * NTHR) {
        int t = idx / (Bv * Ev);
        int rem = idx - t * (Bv * Ev);
        int bb = rem >> 8, e = rem & 255;
        g_decT[t][e * Bv + bb] = dec[idx];
    }
    slot_arrive(128);
    slot_wait(128);

    // ================= step loop =================
    #pragma unroll 1
    for (int t = 0; t < T_DEC; t++) {
        const int par = t & 1;

        // ---------- Phase A: attention ----------
        if (t > 0) {
            slot_wait(2 * (t - 1) + 1);          // h_t globally visible
            s_h[tid]       = g_hHist[t][b * Dv + tid];
            s_h[tid + 256] = g_hHist[t][b * Dv + tid + 256];
        }
        __syncthreads();

        // proj[e] = h . W_att[e,:]: 8 warps x 8 rows (2 passes of 4)
        if (t > 0) {
            const float4* hp = (const float4*)s_h;
            #pragma unroll
            for (int pass = 0; pass < 2; pass++) {
                const int rl = (wid << 3) + pass * 4;
                // L2 tail loads issued first (overlap with SMEM FMAs)
                const float4 fg0 = ((const float4*)(W_att + (size_t)(e0 + rl + 0) * Dv + 384))[lane];
                const float4 fg1 = ((const float4*)(W_att + (size_t)(e0 + rl + 1) * Dv + 384))[lane];
                const float4 fg2 = ((const float4*)(W_att + (size_t)(e0 + rl + 2) * Dv + 384))[lane];
                const float4 fg3 = ((const float4*)(W_att + (size_t)(e0 + rl + 3) * Dv + 384))[lane];
                const float4* s0 = (const float4*)(s_Wa + (rl + 0) * 384);
                const float4* s1 = (const float4*)(s_Wa + (rl + 1) * 384);
                const float4* s2 = (const float4*)(s_Wa + (rl + 2) * 384);
                const float4* s3 = (const float4*)(s_Wa + (rl + 3) * 384);
                float a0 = 0.f, a1 = 0.f, a2 = 0.f, a3 = 0.f;
                #pragma unroll
                for (int i = 0; i < 3; i++) {
                    int k4 = lane + 32 * i;
                    float4 h4 = hp[k4];
                    float4 f0 = s0[k4], f1 = s1[k4], f2 = s2[k4], f3 = s3[k4];
                    a0 = fmaf(f0.x, h4.x, fmaf(f0.y, h4.y, fmaf(f0.z, h4.z, fmaf(f0.w, h4.w, a0))));
                    a1 = fmaf(f1.x, h4.x, fmaf(f1.y, h4.y, fmaf(f1.z, h4.z, fmaf(f1.w, h4.w, a1))));
                    a2 = fmaf(f2.x, h4.x, fmaf(f2.y, h4.y, fmaf(f2.z, h4.z, fmaf(f2.w, h4.w, a2))));
                    a3 = fmaf(f3.x, h4.x, fmaf(f3.y, h4.y, fmaf(f3.z, h4.z, fmaf(f3.w, h4.w, a3))));
                }
                {
                    float4 h4 = hp[lane + 96];
                    a0 = fmaf(fg0.x, h4.x, fmaf(fg0.y, h4.y, fmaf(fg0.z, h4.z, fmaf(fg0.w, h4.w, a0))));
                    a1 = fmaf(fg1.x, h4.x, fmaf(fg1.y, h4.y, fmaf(fg1.z, h4.z, fmaf(fg1.w, h4.w, a1))));
                    a2 = fmaf(fg2.x, h4.x, fmaf(fg2.y, h4.y, fmaf(fg2.z, h4.z, fmaf(fg2.w, h4.w, a2))));
                    a3 = fmaf(fg3.x, h4.x, fmaf(fg3.y, h4.y, fmaf(fg3.z, h4.z, fmaf(fg3.w, h4.w, a3))));
                }
                #pragma unroll
                for (int o = 16; o; o >>= 1) {
                    a0 += __shfl_down_sync(0xffffffffu, a0, o);
                    a1 += __shfl_down_sync(0xffffffffu, a1, o);
                    a2 += __shfl_down_sync(0xffffffffu, a2, o);
                    a3 += __shfl_down_sync(0xffffffffu, a3, o);
                }
                if (lane == 0) {
                    s_proj[rl + 0] = a0; s_proj[rl + 1] = a1;
                    s_proj[rl + 2] = a2; s_proj[rl + 3] = a3;
                }
            }
        } else if (tid < 64) s_proj[tid] = 0.f;
        __syncthreads();

        // softmax pass 1: Z[e] partials (u recomputed later, not stored)
        const int ee = tid & 63, tg = tid >> 6;   // tg in 0..3
        {
            float p = s_proj[ee];
            float z = 0.f;
            #pragma unroll 8
            for (int ti = tg; ti < TENC; ti += 4)
                z += fast_exp2(s_A[ti * 65 + ee] * p);
            s_zp[tid] = z;
        }
        __syncthreads();
        if (tid < 64) {
            float zz = s_zp[tid] + s_zp[64 + tid] + s_zp[128 + tid] + s_zp[192 + tid];
            s_rZ[tid] = 1.f / zz;
        }
        __syncthreads();

        // tw[t] partial over owned e's (thread = encoder time index); u recomputed
        {
            const float* ap = s_A + tid * 65;
            float v = 0.f;
            #pragma unroll 8
            for (int e = 0; e < 64; e++) {
                float u = fast_exp2(ap[e] * s_proj[e]);
                v = fmaf(u, s_rZ[e], v);
            }
            s_twp[tid] = v;
        }
        cl.sync();
        {
            float s = 0.f;
            #pragma unroll
            for (int r = 0; r < 4; r++) {
                const float* rp = cl.map_shared_rank(s_twp, r);
                s += rp[tid];
            }
            s_tw[tid] = s;
        }
        __syncthreads();   // replaces 2nd cl.sync: anti-dep on s_twp ordered by step barriers

        // ctx[e] = ln2 * sum_t tw[t] * a'[t,e]
        {
            float acc = 0.f;
            #pragma unroll 8
            for (int ti = tg; ti < TENC; ti += 4)
                acc = fmaf(s_tw[ti], s_A[ti * 65 + ee], acc);
            s_zp[tid] = acc;
        }
        __syncthreads();
        if (tid < 64) {
            float c = (s_zp[tid] + s_zp[64 + tid] + s_zp[128 + tid] + s_zp[192 + tid]) * LN2;
            g_ctxHist[t][b * Ev + e0 + tid] = c;
            g_ctxT[par][(e0 + tid) * Bv + b] = c;
        }
        slot_arrive(2 * t);                    // ctx-ready (includes syncthreads)

        // ---------- Phase B: GRU, overlapped with the ctx barrier ----------
        const int rg = wid & 3;           // row-group (24 rows)
        const int kh = wid >> 2;          // k-half (64 k) within CTA's quarter
        const int r0 = rg * 24;
        const int kabs0 = q * 128 + kh * 64;
        const float* wbase = s_Wg + r0 * 128 + kh * 64;

        bool zsrc = false;
        const float* src;
        bool needs_ctx = false;
        if (rg < 2) {
            if (kabs0 < 256) {
                zsrc = (t == 0);
                src = g_decT[(t > 0) ? (t - 1) : 0] + kabs0 * Bv;
            } else {
                src = g_ctxT[par] + (kabs0 - 256) * Bv;
                needs_ctx = true;
            }
        } else {
            zsrc = (t == 0);
            src = g_hT[par] + kabs0 * Bv;
        }

        float psum[24];
        if (!needs_ctx) gru_gemv24(src, zsrc, wbase, lane, psum);   // pre: h + dec rows
        slot_wait(2 * t);                                           // all ctx visible
        if (needs_ctx)  gru_gemv24(src, zsrc, wbase, lane, psum);   // post: ctx rows

        // merge the two k-halves into s_gp
        if (wid < 4) {
            #pragma unroll
            for (int j = 0; j < 24; j++) s_gp[(r0 + j) * 32 + lane] = psum[j];
        }
        __syncthreads();
        if (wid >= 4) {
            #pragma unroll
            for (int j = 0; j < 24; j++) s_gp[(r0 + j) * 32 + lane] += psum[j];
        }
        cl.sync();   // DSMEM: peers' s_gp ready (also covers CTA sync)

        // epilogue: CTA q handles local dims [4q, 4q+4), summing the 4 rank partials
        if (tid < 128) {
            const int dl = q * 4 + (tid >> 5);
            const int bb = lane;
            float G[6];
            #pragma unroll
            for (int g = 0; g < 6; g++) {
                float s = 0.f;
                #pragma unroll
                for (int r = 0; r < 4; r++) {
                    const float* rp = cl.map_shared_rank(s_gp, r);
                    s += rp[(g * 16 + dl) * 32 + bb];
                }
                G[g] = s;
            }
            float rg2 = 1.f / (1.f + __expf(-(G[0] + G[3])));
            float zg  = 1.f / (1.f + __expf(-(G[1] + G[4])));
            float ng  = tanhf(G[2] + rg2 * G[5]);
            int d = (b << 4) + dl;
            float hold = (t == 0) ? 0.f : g_hT[par][d * Bv + bb];
            float hnew = fmaxf((1.f - zg) * ng + zg * hold, 0.f);
            g_hT[par ^ 1][d * Bv + bb] = hnew;
            g_hHist[t + 1][bb * Dv + d] = hnew;
        }
        slot_arrive(2 * t + 1);   // h-ready
    }

    slot_wait(2 * (T_DEC - 1) + 1);   // last h visible everywhere

    // ================= final heads pass =================
    // CTA covers 16 (t,b) pairs sharing one t: tP = cid/2, b in [b0, b0+16)
    {
        float* s_WC = sm;               // 27*768 floats
        float* s_P  = sm + 20736;       // 16*772 floats
        const int tP = cid >> 1;
        const int b0 = (cid & 1) * 16;

        for (int idx = tid; idx < 16 * 768; idx += NTHR) {
            int p = idx / 768, i = idx - p * 768;
            int bb = b0 + p;
            float v = (i < 256) ? g_ctxHist[tP][bb * Ev + i]
                                : g_hHist[tP + 1][bb * Dv + (i - 256)];
            s_P[p * 772 + i] = v;
        }
        __syncthreads();

        #pragma unroll 1
        for (int chunk = 0; chunk < 3; chunk++) {
            const int r0h = chunk * 27;
            for (int idx = tid; idx < 27 * 768; idx += NTHR) {
                int j = idx / 768, k = idx - j * 768;
                int rg2 = r0h + j;
                s_WC[idx] = (rg2 < 80) ? W_mel[(size_t)rg2 * 768 + k] : W_gate[k];
            }
            __syncthreads();

            for (int d = tid; d < 27 * 16; d += NTHR) {
                int j = d >> 4, p = d & 15;
                const float4* wr = (const float4*)(s_WC + j * 768);
                const float4* ch = (const float4*)(s_P + p * 772);
                float acc = 0.f;
                #pragma unroll 8
                for (int k4 = 0; k4 < 192; k4++) {
                    float4 w = wr[k4];
                    float4 c = ch[k4];
                    acc = fmaf(w.x, c.x, fmaf(w.y, c.y, fmaf(w.z, c.z, fmaf(w.w, c.w, acc))));
                }
                int rg2 = r0h + j;
                int bb = b0 + p;
                if (rg2 < 80) out[bb * (NMEL * T_DEC) + rg2 * T_DEC + tP] = acc + b_mel[rg2];
                else          out[NMEL * T_DEC * Bv + bb * T_DEC + tP]   = acc + gate_b;
            }
            __syncthreads();
        }
    }

    // final replay-safe barrier, then reset one-shot slot counters
    gen_bar(cl, lead);
    if (tid == 0)
        for (int i = cid; i < NSLOT; i += NCTA) *((unsigned*)&g_slots[i]) = 0u;
}

// ------------------------------------------------------------------
extern "C" void kernel_launch(void* const* d_in, const int* in_sizes, int n_in,
                              void* d_out, int out_size)
{
    const float* dec    = (const float*)d_in[0];
    const float* A      = (const float*)d_in[1];
    const float* W_att  = (const float*)d_in[2];
    const float* W_ih   = (const float*)d_in[3];
    const float* W_hh   = (const float*)d_in[4];
    const float* W_mel  = (const float*)d_in[5];
    const float* b_mel  = (const float*)d_in[6];
    const float* W_gate = (const float*)d_in[7];
    const float* b_gate = (const float*)d_in[8];
    float* out = (float*)d_out;

    cudaFuncSetAttribute(decoder_persistent,
                         cudaFuncAttributeMaxDynamicSharedMemorySize, SMEM_BYTES);

    decoder_persistent<<<NGRID, NTHR, SMEM_BYTES>>>(
        dec, A, W_att, W_ih, W_hh, W_mel, b_mel, W_gate, b_gate, out);
}